// round 7
// baseline (speedup 1.0000x reference)
#include <cuda_runtime.h>
#include <cuda_fp16.h>
#include <math_constants.h>
#include <cstdint>

// ---------------------------------------------------------------- constants
#define NN 64
#define CC 3
#define NCC (NN*CC)        // 192 rows
#define LL 4096
#define KK 128             // shapelets
#define SS 64              // shapelet length
#define WW (LL - SS + 1)   // 4033 valid windows
#define GROUPS 6           // window groups per nc row
#define WPC 704            // windows per CTA (11 tiles of 64; 6*704=4224 >= 4033)
#define TILES 11
#define GRID (NCC*GROUPS)  // 1152 CTAs
#define TMAIN 256

#define STRIP 784          // f32 strip elements (704 + 64 + pad)
#define PSTR  388          // parity-pair words

// ---------------------------------------------------------------- scratch
__device__ uint32_t g_shp[CC*KK*32]; // shapelet fp16 pairs, row-major (32 u32 per k-row)
__device__ float    g_s2[CC*KK];     // ||s||^2
__device__ int      g_minb[NN*KK];   // running min d^2 (int bits)
__device__ int      g_ctr;           // completion counter (zero-init, self-reset)

__device__ __forceinline__ uint32_t packh(float a, float b) {
    __half2 h = __floats2half2_rn(a, b);   // low = a, high = b
    return *(uint32_t*)&h;
}

// ---------------------------------------------------------------- prep (tiny)
__global__ __launch_bounds__(256) void prep_kernel(const float* __restrict__ sh) {
    int t = blockIdx.x * blockDim.x + threadIdx.x;
    int nt = gridDim.x * blockDim.x;
    for (int i = t; i < CC * KK * 32; i += nt) {
        int base = (i >> 5) * SS + (i & 31) * 2;
        g_shp[i] = packh(sh[base], sh[base + 1]);
    }
    for (int i = t; i < CC * KK; i += nt) {
        const float* p = sh + i * SS;
        float s = 0.f;
#pragma unroll
        for (int j = 0; j < SS; j++) s = fmaf(p[j], p[j], s);
        g_s2[i] = s;
    }
    for (int i = t; i < NN * KK; i += nt) g_minb[i] = 0x7F800000;  // +inf
}

// ---------------------------------------------------------------- mma wrappers
__device__ __forceinline__ void mma16816(float& c0, float& c1, float& c2, float& c3,
                                         uint32_t a0, uint32_t a1, uint32_t a2, uint32_t a3,
                                         uint32_t b0, uint32_t b1) {
    asm("mma.sync.aligned.m16n8k16.row.col.f32.f16.f16.f32 "
        "{%0,%1,%2,%3}, {%4,%5,%6,%7}, {%8,%9}, {%0,%1,%2,%3};"
        : "+f"(c0), "+f"(c1), "+f"(c2), "+f"(c3)
        : "r"(a0), "r"(a1), "r"(a2), "r"(a3), "r"(b0), "r"(b1));
}
// out-of-place with zero C: no accumulator init needed
__device__ __forceinline__ void mma16816_z(float& c0, float& c1, float& c2, float& c3,
                                           uint32_t a0, uint32_t a1, uint32_t a2, uint32_t a3,
                                           uint32_t b0, uint32_t b1) {
    float z = 0.f;
    asm("mma.sync.aligned.m16n8k16.row.col.f32.f16.f16.f32 "
        "{%0,%1,%2,%3}, {%4,%5,%6,%7}, {%8,%9}, {%10,%10,%10,%10};"
        : "=f"(c0), "=f"(c1), "=f"(c2), "=f"(c3)
        : "r"(a0), "r"(a1), "r"(a2), "r"(a3), "r"(b0), "r"(b1), "f"(z));
}

// ---------------------------------------------------------------- main
// CTA = (nc row, group of 704 windows = 11 tiles of 64).
// Software-pipelined: HMMA burst of tile t overlaps the epilogue of tile t-1
// (double-buffered accumulators -> tensor pipe never drains on epilogue RAW).
__global__ __launch_bounds__(TMAIN, 2) void main_kernel(const float* __restrict__ x,
                                                        float* __restrict__ out) {
    __shared__ float xs[STRIP];
    __shared__ uint32_t SE[PSTR], SO[PSTR];
    __shared__ float x2s[WPC];
    __shared__ uint32_t As[KK * 33];        // stride-33: conflict-free frag reads

    int b = blockIdx.x;
    int nc = b / GROUPS, grp = b % GROUPS;
    int c = nc % CC, n = nc / CC;
    int tid = threadIdx.x, lane = tid & 31, warp = tid >> 5;
    int wm = warp & 3, wn = warp >> 2;
    int q = lane & 3, g = lane >> 2;

    int ebase = grp * WPC;
    const float* xr = x + nc * LL;

    // 1) stage shapelet tile (channel c) into smem, coalesced
    {
        const uint32_t* src = g_shp + c * (KK * 32);
        for (int i = tid; i < KK * 32; i += TMAIN)
            As[(i >> 5) * 33 + (i & 31)] = src[i];
    }
    // 2) f32 strip (zero-padded past row end)
    for (int i = tid; i < STRIP; i += TMAIN) {
        int gidx = ebase + i;
        xs[i] = (gidx < LL) ? xr[gidx] : 0.f;
    }
    __syncthreads();

    // 3) fp16 parity packs
    for (int i = tid; i < PSTR; i += TMAIN) {
        float e0 = xs[2 * i], e1 = xs[2 * i + 1], e2 = xs[2 * i + 2];
        SE[i] = packh(e0, e1);
        SO[i] = packh(e1, e2);
    }
    // 4) window norms: 3 windows/thread via sliding update (near-exact)
    {
        int w0 = tid * 3;
        if (w0 < WPC) {
            float s = 0.f;
#pragma unroll
            for (int i = 0; i < SS; i++) { float v = xs[w0 + i]; s = fmaf(v, v, s); }
            x2s[w0] = (ebase + w0 < WW) ? s : CUDART_INF_F;
#pragma unroll
            for (int r = 1; r < 3; r++) {
                int w = w0 + r;
                float vin = xs[w + SS - 1], vout = xs[w - 1];
                s = fmaf(vin, vin, fmaf(-vout, vout, s));
                if (w < WPC) x2s[w] = (ebase + w < WW) ? s : CUDART_INF_F;
            }
        }
    }
    __syncthreads();

    // 5) A fragments: regs from smem (conflict-free), rows wm*32..wm*32+31
    uint32_t A[2][4][4];
    float s2v[2][2];
#pragma unroll
    for (int mt = 0; mt < 2; mt++) {
        int r0 = wm * 32 + mt * 16 + g;
        int r1 = r0 + 8;
        const uint32_t* ap0 = As + r0 * 33;
        const uint32_t* ap1 = As + r1 * 33;
#pragma unroll
        for (int ks = 0; ks < 4; ks++) {
            A[mt][ks][0] = ap0[ks * 8 + q];
            A[mt][ks][1] = ap1[ks * 8 + q];
            A[mt][ks][2] = ap0[ks * 8 + q + 4];
            A[mt][ks][3] = ap1[ks * 8 + q + 4];
        }
        s2v[mt][0] = g_s2[c * KK + r0];
        s2v[mt][1] = g_s2[c * KK + r1];
    }

    // per-lane strip pointer (parity of element index = g&1)
    const uint32_t* sp = ((g & 1) ? SO : SE) + (g >> 1) + q + wn * 16;
    int colbase = wn * 32 + q * 2;

    float mn[2][2] = {{CUDART_INF_F, CUDART_INF_F}, {CUDART_INF_F, CUDART_INF_F}};

    float accP[2][4][4];   // ping
    float accQ[2][4][4];   // pong

    // ---- HMMA burst: ks-outer -> 8 independent accumulator chains
#define HMMA_TILE(ACC, T)                                                          \
    do {                                                                           \
        uint32_t Bw[11];                                                           \
        _Pragma("unroll")                                                          \
        for (int j = 0; j < 11; j++) Bw[j] = sp[(T) * 32 + j * 4];                 \
        _Pragma("unroll")                                                          \
        for (int nt = 0; nt < 4; nt++) {                                           \
            mma16816_z(ACC[0][nt][0], ACC[0][nt][1], ACC[0][nt][2], ACC[0][nt][3], \
                       A[0][0][0], A[0][0][1], A[0][0][2], A[0][0][3],             \
                       Bw[nt], Bw[nt + 1]);                                        \
            mma16816_z(ACC[1][nt][0], ACC[1][nt][1], ACC[1][nt][2], ACC[1][nt][3], \
                       A[1][0][0], A[1][0][1], A[1][0][2], A[1][0][3],             \
                       Bw[nt], Bw[nt + 1]);                                        \
        }                                                                          \
        _Pragma("unroll")                                                          \
        for (int ks = 1; ks < 4; ks++) {                                           \
            _Pragma("unroll")                                                      \
            for (int nt = 0; nt < 4; nt++) {                                       \
                mma16816(ACC[0][nt][0], ACC[0][nt][1], ACC[0][nt][2], ACC[0][nt][3], \
                         A[0][ks][0], A[0][ks][1], A[0][ks][2], A[0][ks][3],       \
                         Bw[nt + 2 * ks], Bw[nt + 2 * ks + 1]);                    \
                mma16816(ACC[1][nt][0], ACC[1][nt][1], ACC[1][nt][2], ACC[1][nt][3], \
                         A[1][ks][0], A[1][ks][1], A[1][ks][2], A[1][ks][3],       \
                         Bw[nt + 2 * ks], Bw[nt + 2 * ks + 1]);                    \
            }                                                                      \
        }                                                                          \
    } while (0)

#define EPI_TILE(ACC, T)                                                        \
    do {                                                                        \
        _Pragma("unroll")                                                       \
        for (int nt = 0; nt < 4; nt++) {                                        \
            float2 xv = *(const float2*)&x2s[(T) * 64 + colbase + nt * 8];      \
            mn[0][0] = fminf(mn[0][0], fmaf(-2.f, ACC[0][nt][0], xv.x));        \
            mn[0][0] = fminf(mn[0][0], fmaf(-2.f, ACC[0][nt][1], xv.y));        \
            mn[0][1] = fminf(mn[0][1], fmaf(-2.f, ACC[0][nt][2], xv.x));        \
            mn[0][1] = fminf(mn[0][1], fmaf(-2.f, ACC[0][nt][3], xv.y));        \
            mn[1][0] = fminf(mn[1][0], fmaf(-2.f, ACC[1][nt][0], xv.x));        \
            mn[1][0] = fminf(mn[1][0], fmaf(-2.f, ACC[1][nt][1], xv.y));        \
            mn[1][1] = fminf(mn[1][1], fmaf(-2.f, ACC[1][nt][2], xv.x));        \
            mn[1][1] = fminf(mn[1][1], fmaf(-2.f, ACC[1][nt][3], xv.y));        \
        }                                                                       \
    } while (0)

    // software pipeline over tiles (TILES = 11, odd)
    HMMA_TILE(accP, 0);
#pragma unroll 2
    for (int t = 1; t < TILES; t++) {
        if (t & 1) { HMMA_TILE(accQ, t); EPI_TILE(accP, t - 1); }
        else       { HMMA_TILE(accP, t); EPI_TILE(accQ, t - 1); }
    }
    EPI_TILE(accP, TILES - 1);   // TILES-1 = 10 (even) lives in accP

    // reduce over the 4 lanes sharing the same rows (same g, q = 0..3)
#pragma unroll
    for (int mt = 0; mt < 2; mt++)
#pragma unroll
        for (int h = 0; h < 2; h++) {
            float v = mn[mt][h];
            v = fminf(v, __shfl_xor_sync(0xFFFFFFFFu, v, 1));
            v = fminf(v, __shfl_xor_sync(0xFFFFFFFFu, v, 2));
            if (q == 0) {
                int row = wm * 32 + mt * 16 + h * 8 + g;
                atomicMin(&g_minb[n * KK + row], __float_as_int(v + s2v[mt][h]));
            }
        }

    // last CTA finalizes: sqrt(min d^2) -> out
    __shared__ int lastFlag;
    __threadfence();
    __syncthreads();
    if (tid == 0) lastFlag = (atomicAdd(&g_ctr, 1) == GRID - 1);
    __syncthreads();
    if (lastFlag) {
        __threadfence();
        for (int i = tid; i < NN * KK; i += TMAIN) {
            float d2 = __int_as_float(g_minb[i]);
            out[i] = sqrtf(fmaxf(d2, 0.f));
        }
        __threadfence();
        if (tid == 0) g_ctr = 0;
    }
}

// ---------------------------------------------------------------- launch
extern "C" void kernel_launch(void* const* d_in, const int* in_sizes, int n_in,
                              void* d_out, int out_size) {
    const float* x  = (const float*)d_in[0];
    const float* sh = (const float*)d_in[1];
    if (n_in >= 2 && in_sizes[0] == CC * KK * SS && in_sizes[1] == NN * CC * LL) {
        x  = (const float*)d_in[1];
        sh = (const float*)d_in[0];
    }
    prep_kernel<<<8, 256>>>(sh);
    main_kernel<<<GRID, TMAIN>>>(x, (float*)d_out);
}

// round 8
// speedup vs baseline: 1.0599x; 1.0599x over previous
#include <cuda_runtime.h>
#include <cuda_fp16.h>
#include <math_constants.h>
#include <cstdint>

// ---------------------------------------------------------------- constants
#define NN 64
#define CC 3
#define NCC (NN*CC)        // 192 rows
#define LL 4096
#define KK 128             // shapelets
#define SS 64              // shapelet length
#define WW (LL - SS + 1)   // 4033 valid windows
#define GROUPS 4           // window groups per nc row
#define WPC 1024           // windows per CTA (16 tiles of 64; 4*1024=4096 >= 4033)
#define TILES 16
#define GRID (NCC*GROUPS)  // 768 CTAs
#define TMAIN 256

#define STRIP 1096         // f32 strip elements (1024 + 64 + pad)
#define PSTR  546          // parity-pair words

// ---------------------------------------------------------------- scratch
__device__ uint32_t g_shp[CC*KK*32]; // shapelet fp16 pairs, row-major (32 u32 per k-row)
__device__ float    g_s2[CC*KK];     // ||s||^2
__device__ int      g_minb[NN*KK];   // running min d^2 (int bits)
__device__ int      g_ctr;           // completion counter (zero-init, self-reset)

__device__ __forceinline__ uint32_t packh(float a, float b) {
    __half2 h = __floats2half2_rn(a, b);   // low = a, high = b
    return *(uint32_t*)&h;
}

// ---------------------------------------------------------------- prep (tiny)
__global__ __launch_bounds__(256) void prep_kernel(const float* __restrict__ sh) {
    int t = blockIdx.x * blockDim.x + threadIdx.x;
    int nt = gridDim.x * blockDim.x;
    for (int i = t; i < CC * KK * 32; i += nt) {
        int base = (i >> 5) * SS + (i & 31) * 2;
        g_shp[i] = packh(sh[base], sh[base + 1]);
    }
    for (int i = t; i < CC * KK; i += nt) {
        const float* p = sh + i * SS;
        float s = 0.f;
#pragma unroll
        for (int j = 0; j < SS; j++) s = fmaf(p[j], p[j], s);
        g_s2[i] = s;
    }
    for (int i = t; i < NN * KK; i += nt) g_minb[i] = 0x7F800000;  // +inf
}

// ---------------------------------------------------------------- mma wrappers
__device__ __forceinline__ void mma16816(float& c0, float& c1, float& c2, float& c3,
                                         uint32_t a0, uint32_t a1, uint32_t a2, uint32_t a3,
                                         uint32_t b0, uint32_t b1) {
    asm("mma.sync.aligned.m16n8k16.row.col.f32.f16.f16.f32 "
        "{%0,%1,%2,%3}, {%4,%5,%6,%7}, {%8,%9}, {%0,%1,%2,%3};"
        : "+f"(c0), "+f"(c1), "+f"(c2), "+f"(c3)
        : "r"(a0), "r"(a1), "r"(a2), "r"(a3), "r"(b0), "r"(b1));
}
// out-of-place with zero C: no accumulator init needed
__device__ __forceinline__ void mma16816_z(float& c0, float& c1, float& c2, float& c3,
                                           uint32_t a0, uint32_t a1, uint32_t a2, uint32_t a3,
                                           uint32_t b0, uint32_t b1) {
    float z = 0.f;
    asm("mma.sync.aligned.m16n8k16.row.col.f32.f16.f16.f32 "
        "{%0,%1,%2,%3}, {%4,%5,%6,%7}, {%8,%9}, {%10,%10,%10,%10};"
        : "=f"(c0), "=f"(c1), "=f"(c2), "=f"(c3)
        : "r"(a0), "r"(a1), "r"(a2), "r"(a3), "r"(b0), "r"(b1), "f"(z));
}

// ---------------------------------------------------------------- main
// CTA = (nc row, group of 1024 windows = 16 tiles of 64).
// Warp-phase staggering: warp w visits tile (t + 2w) & 15 -> HMMA bursts of
// some warps overlap epilogues of others (convoy broken, tensor pipe fed).
__global__ __launch_bounds__(TMAIN, 3) void main_kernel(const float* __restrict__ x,
                                                        float* __restrict__ out) {
    __shared__ float xs[STRIP];
    __shared__ uint32_t SE[PSTR], SO[PSTR];
    __shared__ float x2s[WPC];
    __shared__ uint32_t As[KK * 33];        // stride-33: conflict-free frag reads

    int b = blockIdx.x;
    int nc = b / GROUPS, grp = b % GROUPS;
    int c = nc % CC, n = nc / CC;
    int tid = threadIdx.x, lane = tid & 31, warp = tid >> 5;
    int wm = warp & 3, wn = warp >> 2;
    int q = lane & 3, g = lane >> 2;

    int ebase = grp * WPC;
    const float* xr = x + nc * LL;

    // 1) stage shapelet tile (channel c) into smem, coalesced
    {
        const uint32_t* src = g_shp + c * (KK * 32);
        for (int i = tid; i < KK * 32; i += TMAIN)
            As[(i >> 5) * 33 + (i & 31)] = src[i];
    }
    // 2) f32 strip (zero-padded past row end)
    for (int i = tid; i < STRIP; i += TMAIN) {
        int gidx = ebase + i;
        xs[i] = (gidx < LL) ? xr[gidx] : 0.f;
    }
    __syncthreads();

    // 3) fp16 parity packs
    for (int i = tid; i < PSTR; i += TMAIN) {
        float e0 = xs[2 * i], e1 = xs[2 * i + 1], e2 = xs[2 * i + 2];
        SE[i] = packh(e0, e1);
        SO[i] = packh(e1, e2);
    }
    // 4) window norms: 4 windows/thread via sliding update (near-exact)
    {
        int w0 = tid * 4;
        float s = 0.f;
#pragma unroll
        for (int i = 0; i < SS; i++) { float v = xs[w0 + i]; s = fmaf(v, v, s); }
        x2s[w0] = (ebase + w0 < WW) ? s : CUDART_INF_F;
#pragma unroll
        for (int r = 1; r < 4; r++) {
            int w = w0 + r;
            float vin = xs[w + SS - 1], vout = xs[w - 1];
            s = fmaf(vin, vin, fmaf(-vout, vout, s));
            x2s[w] = (ebase + w < WW) ? s : CUDART_INF_F;
        }
    }
    __syncthreads();

    // 5) A fragments: regs from smem (conflict-free), rows wm*32..wm*32+31
    uint32_t A[2][4][4];
    float s2v[2][2];
#pragma unroll
    for (int mt = 0; mt < 2; mt++) {
        int r0 = wm * 32 + mt * 16 + g;
        int r1 = r0 + 8;
        const uint32_t* ap0 = As + r0 * 33;
        const uint32_t* ap1 = As + r1 * 33;
#pragma unroll
        for (int ks = 0; ks < 4; ks++) {
            A[mt][ks][0] = ap0[ks * 8 + q];
            A[mt][ks][1] = ap1[ks * 8 + q];
            A[mt][ks][2] = ap0[ks * 8 + q + 4];
            A[mt][ks][3] = ap1[ks * 8 + q + 4];
        }
        s2v[mt][0] = g_s2[c * KK + r0];
        s2v[mt][1] = g_s2[c * KK + r1];
    }

    // per-lane strip pointer (parity of element index = g&1)
    const uint32_t* sp = ((g & 1) ? SO : SE) + (g >> 1) + q + wn * 16;
    int colbase = wn * 32 + q * 2;
    int tphase = 2 * warp;            // stagger: warps spread across 16 tiles

    float mn[2][2] = {{CUDART_INF_F, CUDART_INF_F}, {CUDART_INF_F, CUDART_INF_F}};

#pragma unroll 1
    for (int t0 = 0; t0 < TILES; t0++) {
        int t = (t0 + tphase) & (TILES - 1);

        // 11 distinct B words cover all (nt, ks) fragments of this tile
        uint32_t Bw[11];
#pragma unroll
        for (int j = 0; j < 11; j++) Bw[j] = sp[t * 32 + j * 4];

#pragma unroll
        for (int nt = 0; nt < 4; nt++) {
            float a0c[4], a1c[4];
            mma16816_z(a0c[0], a0c[1], a0c[2], a0c[3],
                       A[0][0][0], A[0][0][1], A[0][0][2], A[0][0][3],
                       Bw[nt], Bw[nt + 1]);
            mma16816_z(a1c[0], a1c[1], a1c[2], a1c[3],
                       A[1][0][0], A[1][0][1], A[1][0][2], A[1][0][3],
                       Bw[nt], Bw[nt + 1]);
#pragma unroll
            for (int ks = 1; ks < 4; ks++) {
                mma16816(a0c[0], a0c[1], a0c[2], a0c[3],
                         A[0][ks][0], A[0][ks][1], A[0][ks][2], A[0][ks][3],
                         Bw[nt + 2 * ks], Bw[nt + 2 * ks + 1]);
                mma16816(a1c[0], a1c[1], a1c[2], a1c[3],
                         A[1][ks][0], A[1][ks][1], A[1][ks][2], A[1][ks][3],
                         Bw[nt + 2 * ks], Bw[nt + 2 * ks + 1]);
            }
            // epilogue: min(x2[w] - 2*dot); +s2 folded at the end
            float2 xv = *(const float2*)&x2s[t * 64 + colbase + nt * 8];
            mn[0][0] = fminf(mn[0][0], fmaf(-2.f, a0c[0], xv.x));
            mn[0][0] = fminf(mn[0][0], fmaf(-2.f, a0c[1], xv.y));
            mn[0][1] = fminf(mn[0][1], fmaf(-2.f, a0c[2], xv.x));
            mn[0][1] = fminf(mn[0][1], fmaf(-2.f, a0c[3], xv.y));
            mn[1][0] = fminf(mn[1][0], fmaf(-2.f, a1c[0], xv.x));
            mn[1][0] = fminf(mn[1][0], fmaf(-2.f, a1c[1], xv.y));
            mn[1][1] = fminf(mn[1][1], fmaf(-2.f, a1c[2], xv.x));
            mn[1][1] = fminf(mn[1][1], fmaf(-2.f, a1c[3], xv.y));
        }
    }

    // reduce over the 4 lanes sharing the same rows (same g, q = 0..3)
#pragma unroll
    for (int mt = 0; mt < 2; mt++)
#pragma unroll
        for (int h = 0; h < 2; h++) {
            float v = mn[mt][h];
            v = fminf(v, __shfl_xor_sync(0xFFFFFFFFu, v, 1));
            v = fminf(v, __shfl_xor_sync(0xFFFFFFFFu, v, 2));
            if (q == 0) {
                int row = wm * 32 + mt * 16 + h * 8 + g;
                atomicMin(&g_minb[n * KK + row], __float_as_int(v + s2v[mt][h]));
            }
        }

    // last CTA finalizes: sqrt(min d^2) -> out
    __shared__ int lastFlag;
    __threadfence();
    __syncthreads();
    if (tid == 0) lastFlag = (atomicAdd(&g_ctr, 1) == GRID - 1);
    __syncthreads();
    if (lastFlag) {
        __threadfence();
        for (int i = tid; i < NN * KK; i += TMAIN) {
            float d2 = __int_as_float(g_minb[i]);
            out[i] = sqrtf(fmaxf(d2, 0.f));
        }
        __threadfence();
        if (tid == 0) g_ctr = 0;
    }
}

// ---------------------------------------------------------------- launch
extern "C" void kernel_launch(void* const* d_in, const int* in_sizes, int n_in,
                              void* d_out, int out_size) {
    const float* x  = (const float*)d_in[0];
    const float* sh = (const float*)d_in[1];
    if (n_in >= 2 && in_sizes[0] == CC * KK * SS && in_sizes[1] == NN * CC * LL) {
        x  = (const float*)d_in[1];
        sh = (const float*)d_in[0];
    }
    prep_kernel<<<8, 256>>>(sh);
    main_kernel<<<GRID, TMAIN>>>(x, (float*)d_out);
}